// round 14
// baseline (speedup 1.0000x reference)
#include <cuda_runtime.h>

// 4-qubit statevector VQC, bidirectional split + split producer/consumer
// barriers (R14).
//   amp[j] = < (L9..L5)^† e_j | (L4..L0) v >,  L_d = B_d A_d P
//   (P = composed 4-CNOT ring permutation; math verified R2-R13)
//
// 224 threads:
//  Warp 0:    forward half (layers 0-4, 10 gather-steps) -> w -> smem.
//             Needs ONLY forward rows 0-39  -> waits on barrier 2.
//  Warps 1-3: adjoint half for e_0, e_2, e_15 (layers 9..5, 10 gather-steps)
//             + final 16-lane dot. Need ONLY adjoint rows 40-79 -> barrier 3.
//  Warps 4-6: producers, one Kronecker row per lane (rows 0-79 over lanes
//             128-207). bar.arrive (non-blocking) on the barrier(s) covering
//             the rows they built, then exit:
//               warp 4 (rows 0-31)  -> arrive barrier 2
//               warp 5 (rows 32-63) -> arrive barrier 2 AND barrier 3
//               warp 6 (rows 64-79) -> arrive barrier 3
//  Barrier 2: count 96  (warps 0,4,5).  Barrier 3: count 160 (warps 1,2,3,5,6).
//  Barrier 1: count 128 (warps 0-3), wbuf handoff before the final dot.

__global__ void __launch_bounds__(224, 1)
vqc_kernel(const float* __restrict__ psi,
           const float* __restrict__ ring,
           const float* __restrict__ prx,
           const float* __restrict__ pry,
           const float* __restrict__ prz,
           float* __restrict__ out) {
    __shared__ float4 Rows[160];   // 80 rows x 2 float4
    __shared__ float2 wbuf[16];    // forward-half state
    const unsigned FULL = 0xFFFFFFFFu;
    const int l = threadIdx.x;     // 0..223
    const int k = l & 15;
    const int wid = l >> 5;

    auto perm = [](int j) {        // sigma: composed CNOT ring (gather source)
        j = (j & 1) ? (j ^ 8) : j;
        j = (j & 2) ? (j ^ 1) : j;
        j = (j & 4) ? (j ^ 2) : j;
        j = (j & 8) ? (j ^ 4) : j;
        return j;
    };
    auto invperm = [](int j) {     // sigma^{-1}
        j = (j & 8) ? (j ^ 4) : j;
        j = (j & 4) ? (j ^ 2) : j;
        j = (j & 2) ? (j ^ 1) : j;
        j = (j & 1) ? (j ^ 8) : j;
        return j;
    };

    float re = 0.0f, im = 0.0f;

    if (l >= 128) {
        // ---- producers (warps 4-6): one Kronecker row per lane ----
        int idx = l - 128;                       // 0..95 (lanes 208+ idle)
        if (idx < 80) {
            int d, p, r, adj;
            if (idx < 40) {                      // forward rows, layers 0-4
                d = idx >> 3; int w = idx & 7; p = w >> 2; r = w & 3; adj = 0;
            } else {                             // adjoint rows, layers 5-9
                int b2 = idx - 40;
                d = 5 + (b2 >> 3); int w = b2 & 7;
                int s = w >> 2;                  // s=0: B^† (pair 1), s=1: A^† (pair 0)
                p = 1 - s; r = w & 3; adj = 1;
            }
            int iA = d * 4 + 2 * p, iB = iA + 1;

            float c1, s1, c2, s2, c3, s3;
            __sincosf(0.5f * prx[iA], &s1, &c1);
            __sincosf(0.5f * pry[iA], &s2, &c2);
            __sincosf(0.5f * prz[iA], &s3, &c3);
            float p1 = c2 * c1, p2 = s2 * s1, p3 = s2 * c1, p4 = c2 * s1;
            float A00re =  fmaf(c3, p1,  s3 * p2);
            float A00im =  fmaf(c3, p2, -s3 * p1);
            float A01re = -fmaf(c3, p3,  s3 * p4);
            float A01im =  fmaf(s3, p3, -c3 * p4);

            __sincosf(0.5f * prx[iB], &s1, &c1);
            __sincosf(0.5f * pry[iB], &s2, &c2);
            __sincosf(0.5f * prz[iB], &s3, &c3);
            p1 = c2 * c1; p2 = s2 * s1; p3 = s2 * c1; p4 = c2 * s1;
            float B00re =  fmaf(c3, p1,  s3 * p2);
            float B00im =  fmaf(c3, p2, -s3 * p1);
            float B01re = -fmaf(c3, p3,  s3 * p4);
            float B01im =  fmaf(s3, p3, -c3 * p4);

            if (adj) {  // M^† of SU(2) [[g00,g01],[-g01*,g00*]] -> (g00*, -g01)
                A00im = -A00im; A01re = -A01re; A01im = -A01im;
                B00im = -B00im; B01re = -B01re; B01im = -B01im;
            }

            // row a of SU(2) M: a==0 -> (g00,g01); a==1 -> (-g01*, g00*)
            int a = r >> 1, b = r & 1;
            float ar0 = a ? -A01re : A00re, ai0 = a ?  A01im : A00im;
            float ar1 = a ?  A00re : A01re, ai1 = a ? -A00im : A01im;
            float br0 = b ? -B01re : B00re, bi0 = b ?  B01im : B00im;
            float br1 = b ?  B00re : B01re, bi1 = b ? -B00im : B01im;

            float g0r = ar0 * br0 - ai0 * bi0, g0i = ar0 * bi0 + ai0 * br0;
            float g1r = ar0 * br1 - ai0 * bi1, g1i = ar0 * bi1 + ai0 * br1;
            float g2r = ar1 * br0 - ai1 * bi0, g2i = ar1 * bi0 + ai1 * br0;
            float g3r = ar1 * br1 - ai1 * bi1, g3i = ar1 * bi1 + ai1 * br1;
            Rows[idx * 2 + 0] = make_float4(g0r, g0i, g1r, g1i);
            Rows[idx * 2 + 1] = make_float4(g2r, g2i, g3r, g3i);
        }
        // non-blocking arrivals on the barrier(s) covering this warp's rows
        if (wid == 4) {
            asm volatile("bar.arrive 2, 96;" ::: "memory");
        } else if (wid == 5) {
            asm volatile("bar.arrive 2, 96;"  ::: "memory");
            asm volatile("bar.arrive 3, 160;" ::: "memory");
        } else { // wid == 6
            asm volatile("bar.arrive 3, 160;" ::: "memory");
        }
        return;
    }

    if (l < 32) {
        // ---- warp 0: encoded initial product state ----
        float4 rA4 = reinterpret_cast<const float4*>(ring)[0];
        float4 rB4 = reinterpret_cast<const float4*>(ring)[1];
        float pc = 1.0f, ps = 0.0f;
        float pa = (l < 4) ? psi[l] : 0.0f;
        __sincosf(0.5f * pa, &ps, &pc);
        float rr[4][2] = { { rA4.x, rA4.y }, { rA4.z, rA4.w },
                           { rB4.x, rB4.y }, { rB4.z, rB4.w } };
        float vre[4], vim[4];
#pragma unroll
        for (int n = 0; n < 4; n++) {
            float cn = __shfl_sync(FULL, pc, n);
            float sn = __shfl_sync(FULL, ps, n);
            int b = (k >> (3 - n)) & 1;
            vre[n] =  cn * rr[n][b];
            vim[n] = -sn * rr[n][b ^ 1];
        }
        float are = vre[0] * vre[1] - vim[0] * vim[1];
        float aim = vre[0] * vim[1] + vim[0] * vre[1];
        float bre = vre[2] * vre[3] - vim[2] * vim[3];
        float bim = vre[2] * vim[3] + vim[2] * vre[3];
        re = are * bre - aim * bim;
        im = are * bim + aim * bre;
    } else {
        // ---- warps 1-3: u = e_j ----
        int j = (wid == 1) ? 0 : (wid == 2) ? 2 : 15;
        re = (k == j) ? 1.0f : 0.0f;
        im = 0.0f;
    }

    // complex 4-term gather step: out = sum_j Row[j] * x[src_j]
    #define GSTEP(BASE, S0, S1, S2, S3)                                        \
    {                                                                          \
        float4 e0 = Rows[(BASE) * 2], e1 = Rows[(BASE) * 2 + 1];               \
        float x0 = __shfl_sync(FULL, re, S0), y0 = __shfl_sync(FULL, im, S0);  \
        float x1 = __shfl_sync(FULL, re, S1), y1 = __shfl_sync(FULL, im, S1);  \
        float x2 = __shfl_sync(FULL, re, S2), y2 = __shfl_sync(FULL, im, S2);  \
        float x3 = __shfl_sync(FULL, re, S3), y3 = __shfl_sync(FULL, im, S3);  \
        float pr0 = e0.x * x0; pr0 = fmaf(-e0.y, y0, pr0);                     \
        float pr1 = e0.z * x1; pr1 = fmaf(-e0.w, y1, pr1);                     \
        float pr2 = e1.x * x2; pr2 = fmaf(-e1.y, y2, pr2);                     \
        float pr3 = e1.z * x3; pr3 = fmaf(-e1.w, y3, pr3);                     \
        float pi0 = e0.x * y0; pi0 = fmaf(e0.y, x0, pi0);                      \
        float pi1 = e0.z * y1; pi1 = fmaf(e0.w, x1, pi1);                      \
        float pi2 = e1.x * y2; pi2 = fmaf(e1.y, x2, pi2);                      \
        float pi3 = e1.z * y3; pi3 = fmaf(e1.w, x3, pi3);                      \
        re = (pr0 + pr1) + (pr2 + pr3);                                        \
        im = (pi0 + pi1) + (pi2 + pi3);                                        \
    }

    if (l < 32) {
        // wait only for forward rows (warps 4,5)
        asm volatile("bar.sync 2, 96;" ::: "memory");
        // ---- forward half: layers 0-4 (sigma fused into step A) ----
        const int sA0 = perm((k & 3) | 0),  sA1 = perm((k & 3) | 4);
        const int sA2 = perm((k & 3) | 8),  sA3 = perm((k & 3) | 12);
        const int rAi = (k >> 2) & 3, rBi = k & 3;
        const int sB0 = (k & 12) | 0, sB1 = (k & 12) | 1;
        const int sB2 = (k & 12) | 2, sB3 = (k & 12) | 3;
#pragma unroll
        for (int d = 0; d < 5; d++) {
            GSTEP(d * 8 + rAi,     sA0, sA1, sA2, sA3);
            GSTEP(d * 8 + 4 + rBi, sB0, sB1, sB2, sB3);
        }
        if (l < 16) wbuf[k] = make_float2(re, im);
        asm volatile("bar.sync 1, 128;" ::: "memory");   // wbuf handoff
    } else {
        // wait only for adjoint rows (warps 5,6)
        asm volatile("bar.sync 3, 160;" ::: "memory");
        // ---- adjoint half: layers 9 down to 5 ----
        // per layer: B^† (bits 2,1), then A^† (bits 8,4);
        // P^{-1} between layers fused into the next B^†'s sources.
        const int rBi = k & 3, rAi = (k >> 2) & 3;
        const int bp0 = (k & 12) | 0, bp1 = (k & 12) | 1;
        const int bp2 = (k & 12) | 2, bp3 = (k & 12) | 3;
        const int bi0 = invperm(bp0), bi1 = invperm(bp1);
        const int bi2 = invperm(bp2), bi3 = invperm(bp3);
        const int ap0 = (k & 3) | 0,  ap1 = (k & 3) | 4;
        const int ap2 = (k & 3) | 8,  ap3 = (k & 3) | 12;
        // d = 9: plain B^† sources
        GSTEP(40 + 4 * 8 + rBi,     bp0, bp1, bp2, bp3);
        GSTEP(40 + 4 * 8 + 4 + rAi, ap0, ap1, ap2, ap3);
#pragma unroll
        for (int d = 8; d >= 5; d--) {
            GSTEP(40 + (d - 5) * 8 + rBi,     bi0, bi1, bi2, bi3);
            GSTEP(40 + (d - 5) * 8 + 4 + rAi, ap0, ap1, ap2, ap3);
        }
        asm volatile("bar.sync 1, 128;" ::: "memory");   // wbuf handoff

        // ---- dot product: amp_j = sum_m conj(u[m]) * w[sigma(m)] ----
        float2 wv = wbuf[perm(k)];
        float tre = fmaf(re, wv.x,  im * wv.y);
        float tim = fmaf(re, wv.y, -im * wv.x);
#pragma unroll
        for (int m = 1; m < 16; m <<= 1) {
            tre += __shfl_xor_sync(FULL, tre, m);
            tim += __shfl_xor_sync(FULL, tim, m);
        }
        if ((l & 31) == 0) out[wid - 1] = fmaf(tre, tre, tim * tim);
    }
    #undef GSTEP
}

extern "C" void kernel_launch(void* const* d_in, const int* in_sizes, int n_in,
                              void* d_out, int out_size) {
    const float* psi  = (const float*)d_in[0];
    const float* ring = (const float*)d_in[1];
    const float* prx  = (const float*)d_in[2];
    const float* pry  = (const float*)d_in[3];
    const float* prz  = (const float*)d_in[4];
    vqc_kernel<<<1, 224>>>(psi, ring, prx, pry, prz, (float*)d_out);
}

// round 15
// speedup vs baseline: 1.0338x; 1.0338x over previous
#include <cuda_runtime.h>

// 4-qubit statevector VQC, bidirectional split — FINAL CONVERGED KERNEL.
// Exact champion configuration, measured dur_us 6.624/6.624/6.656 across
// three submissions (R7, R12, R13); all perturbations (R8-R11, R14) were
// neutral or regressed.
//
//   amp[j] = < (L9..L5)^† e_j | (L4..L0) v >,  L_d = B_d A_d P
//   (P = composed 4-CNOT ring permutation; math verified R2-R14)
//
// Warp 0: forward half (layers 0-4, 10 gather-steps) -> w, stored to smem.
// Warps 1-3: adjoint half for e_0, e_2, e_15 (layers 9..5, 10 gather-steps),
//   concurrent on their own SMSPs; trailing CNOT-permutation folded into the
//   final dot product's gather index.
// Warps 4-7: dedicated producers (load-bearing for overlap, per R10), one
//   Kronecker pair-matrix row per lane (80 rows: 40 forward + 40 adjoint;
//   adjoint 2x2 = same SU(2) builder with 3 sign flips).
// Full-block __syncthreads barriers (named/split barriers regressed, R14).

__global__ void __launch_bounds__(256, 1)
vqc_kernel(const float* __restrict__ psi,
           const float* __restrict__ ring,
           const float* __restrict__ prx,
           const float* __restrict__ pry,
           const float* __restrict__ prz,
           float* __restrict__ out) {
    __shared__ float4 Rows[160];   // 80 rows x 2 float4
    __shared__ float2 wbuf[16];    // forward-half state
    const unsigned FULL = 0xFFFFFFFFu;
    const int l = threadIdx.x;     // 0..255
    const int k = l & 15;
    const int wid = l >> 5;

    auto perm = [](int j) {        // sigma: composed CNOT ring (gather source)
        j = (j & 1) ? (j ^ 8) : j;
        j = (j & 2) ? (j ^ 1) : j;
        j = (j & 4) ? (j ^ 2) : j;
        j = (j & 8) ? (j ^ 4) : j;
        return j;
    };
    auto invperm = [](int j) {     // sigma^{-1}
        j = (j & 8) ? (j ^ 4) : j;
        j = (j & 4) ? (j ^ 2) : j;
        j = (j & 2) ? (j ^ 1) : j;
        j = (j & 1) ? (j ^ 8) : j;
        return j;
    };

    float re = 0.0f, im = 0.0f;

    if (l >= 128) {
        // ---- producers: one Kronecker row per lane ----
        int idx = l - 128;                       // 0..79 (lanes 208+ idle)
        if (idx < 80) {
            int d, p, r, adj;
            if (idx < 40) {                      // forward rows, layers 0-4
                d = idx >> 3; int w = idx & 7; p = w >> 2; r = w & 3; adj = 0;
            } else {                             // adjoint rows, layers 5-9
                int b2 = idx - 40;
                d = 5 + (b2 >> 3); int w = b2 & 7;
                int s = w >> 2;                  // s=0: B^† (pair 1), s=1: A^† (pair 0)
                p = 1 - s; r = w & 3; adj = 1;
            }
            int iA = d * 4 + 2 * p, iB = iA + 1;

            float c1, s1, c2, s2, c3, s3;
            __sincosf(0.5f * prx[iA], &s1, &c1);
            __sincosf(0.5f * pry[iA], &s2, &c2);
            __sincosf(0.5f * prz[iA], &s3, &c3);
            float p1 = c2 * c1, p2 = s2 * s1, p3 = s2 * c1, p4 = c2 * s1;
            float A00re =  fmaf(c3, p1,  s3 * p2);
            float A00im =  fmaf(c3, p2, -s3 * p1);
            float A01re = -fmaf(c3, p3,  s3 * p4);
            float A01im =  fmaf(s3, p3, -c3 * p4);

            __sincosf(0.5f * prx[iB], &s1, &c1);
            __sincosf(0.5f * pry[iB], &s2, &c2);
            __sincosf(0.5f * prz[iB], &s3, &c3);
            p1 = c2 * c1; p2 = s2 * s1; p3 = s2 * c1; p4 = c2 * s1;
            float B00re =  fmaf(c3, p1,  s3 * p2);
            float B00im =  fmaf(c3, p2, -s3 * p1);
            float B01re = -fmaf(c3, p3,  s3 * p4);
            float B01im =  fmaf(s3, p3, -c3 * p4);

            if (adj) {  // M^† of SU(2) [[g00,g01],[-g01*,g00*]] -> (g00*, -g01)
                A00im = -A00im; A01re = -A01re; A01im = -A01im;
                B00im = -B00im; B01re = -B01re; B01im = -B01im;
            }

            // row a of SU(2) M: a==0 -> (g00,g01); a==1 -> (-g01*, g00*)
            int a = r >> 1, b = r & 1;
            float ar0 = a ? -A01re : A00re, ai0 = a ?  A01im : A00im;
            float ar1 = a ?  A00re : A01re, ai1 = a ? -A00im : A01im;
            float br0 = b ? -B01re : B00re, bi0 = b ?  B01im : B00im;
            float br1 = b ?  B00re : B01re, bi1 = b ? -B00im : B01im;

            float g0r = ar0 * br0 - ai0 * bi0, g0i = ar0 * bi0 + ai0 * br0;
            float g1r = ar0 * br1 - ai0 * bi1, g1i = ar0 * bi1 + ai0 * br1;
            float g2r = ar1 * br0 - ai1 * bi0, g2i = ar1 * bi0 + ai1 * br0;
            float g3r = ar1 * br1 - ai1 * bi1, g3i = ar1 * bi1 + ai1 * br1;
            Rows[idx * 2 + 0] = make_float4(g0r, g0i, g1r, g1i);
            Rows[idx * 2 + 1] = make_float4(g2r, g2i, g3r, g3i);
        }
    } else if (l < 32) {
        // ---- warp 0: encoded initial product state ----
        float4 rA4 = reinterpret_cast<const float4*>(ring)[0];
        float4 rB4 = reinterpret_cast<const float4*>(ring)[1];
        float pc = 1.0f, ps = 0.0f;
        float pa = (l < 4) ? psi[l] : 0.0f;
        __sincosf(0.5f * pa, &ps, &pc);
        float rr[4][2] = { { rA4.x, rA4.y }, { rA4.z, rA4.w },
                           { rB4.x, rB4.y }, { rB4.z, rB4.w } };
        float vre[4], vim[4];
#pragma unroll
        for (int n = 0; n < 4; n++) {
            float cn = __shfl_sync(FULL, pc, n);
            float sn = __shfl_sync(FULL, ps, n);
            int b = (k >> (3 - n)) & 1;
            vre[n] =  cn * rr[n][b];
            vim[n] = -sn * rr[n][b ^ 1];
        }
        float are = vre[0] * vre[1] - vim[0] * vim[1];
        float aim = vre[0] * vim[1] + vim[0] * vre[1];
        float bre = vre[2] * vre[3] - vim[2] * vim[3];
        float bim = vre[2] * vim[3] + vim[2] * vre[3];
        re = are * bre - aim * bim;
        im = are * bim + aim * bre;
    } else {
        // ---- warps 1-3: u = e_j ----
        int j = (wid == 1) ? 0 : (wid == 2) ? 2 : 15;
        re = (k == j) ? 1.0f : 0.0f;
        im = 0.0f;
    }

    __syncthreads();   // Rows ready

    // complex 4-term gather step: out = sum_j Row[j] * x[src_j]
    #define GSTEP(BASE, S0, S1, S2, S3)                                        \
    {                                                                          \
        float4 e0 = Rows[(BASE) * 2], e1 = Rows[(BASE) * 2 + 1];               \
        float x0 = __shfl_sync(FULL, re, S0), y0 = __shfl_sync(FULL, im, S0);  \
        float x1 = __shfl_sync(FULL, re, S1), y1 = __shfl_sync(FULL, im, S1);  \
        float x2 = __shfl_sync(FULL, re, S2), y2 = __shfl_sync(FULL, im, S2);  \
        float x3 = __shfl_sync(FULL, re, S3), y3 = __shfl_sync(FULL, im, S3);  \
        float pr0 = e0.x * x0; pr0 = fmaf(-e0.y, y0, pr0);                     \
        float pr1 = e0.z * x1; pr1 = fmaf(-e0.w, y1, pr1);                     \
        float pr2 = e1.x * x2; pr2 = fmaf(-e1.y, y2, pr2);                     \
        float pr3 = e1.z * x3; pr3 = fmaf(-e1.w, y3, pr3);                     \
        float pi0 = e0.x * y0; pi0 = fmaf(e0.y, x0, pi0);                      \
        float pi1 = e0.z * y1; pi1 = fmaf(e0.w, x1, pi1);                      \
        float pi2 = e1.x * y2; pi2 = fmaf(e1.y, x2, pi2);                      \
        float pi3 = e1.z * y3; pi3 = fmaf(e1.w, x3, pi3);                      \
        re = (pr0 + pr1) + (pr2 + pr3);                                        \
        im = (pi0 + pi1) + (pi2 + pi3);                                        \
    }

    if (l < 32) {
        // ---- forward half: layers 0-4 (sigma fused into step A) ----
        const int sA0 = perm((k & 3) | 0),  sA1 = perm((k & 3) | 4);
        const int sA2 = perm((k & 3) | 8),  sA3 = perm((k & 3) | 12);
        const int rAi = (k >> 2) & 3, rBi = k & 3;
        const int sB0 = (k & 12) | 0, sB1 = (k & 12) | 1;
        const int sB2 = (k & 12) | 2, sB3 = (k & 12) | 3;
#pragma unroll
        for (int d = 0; d < 5; d++) {
            GSTEP(d * 8 + rAi,     sA0, sA1, sA2, sA3);
            GSTEP(d * 8 + 4 + rBi, sB0, sB1, sB2, sB3);
        }
        if (l < 16) wbuf[k] = make_float2(re, im);
    } else if (l < 128) {
        // ---- adjoint half: layers 9 down to 5 ----
        // per layer: B^† (bits 2,1), then A^† (bits 8,4);
        // P^{-1} between layers fused into the next B^†'s sources.
        const int rBi = k & 3, rAi = (k >> 2) & 3;
        const int bp0 = (k & 12) | 0, bp1 = (k & 12) | 1;
        const int bp2 = (k & 12) | 2, bp3 = (k & 12) | 3;
        const int bi0 = invperm(bp0), bi1 = invperm(bp1);
        const int bi2 = invperm(bp2), bi3 = invperm(bp3);
        const int ap0 = (k & 3) | 0,  ap1 = (k & 3) | 4;
        const int ap2 = (k & 3) | 8,  ap3 = (k & 3) | 12;
        // d = 9: plain B^† sources
        GSTEP(40 + 4 * 8 + rBi,     bp0, bp1, bp2, bp3);
        GSTEP(40 + 4 * 8 + 4 + rAi, ap0, ap1, ap2, ap3);
#pragma unroll
        for (int d = 8; d >= 5; d--) {
            GSTEP(40 + (d - 5) * 8 + rBi,     bi0, bi1, bi2, bi3);
            GSTEP(40 + (d - 5) * 8 + 4 + rAi, ap0, ap1, ap2, ap3);
        }
    }

    __syncthreads();   // wbuf ready

    if (wid >= 1 && wid <= 3) {
        // ---- dot product: amp_j = sum_m conj(u[m]) * w[sigma(m)] ----
        float2 wv = wbuf[perm(k)];
        float tre = fmaf(re, wv.x,  im * wv.y);
        float tim = fmaf(re, wv.y, -im * wv.x);
#pragma unroll
        for (int m = 1; m < 16; m <<= 1) {
            tre += __shfl_xor_sync(FULL, tre, m);
            tim += __shfl_xor_sync(FULL, tim, m);
        }
        if ((l & 31) == 0) out[wid - 1] = fmaf(tre, tre, tim * tim);
    }
    #undef GSTEP
}

extern "C" void kernel_launch(void* const* d_in, const int* in_sizes, int n_in,
                              void* d_out, int out_size) {
    const float* psi  = (const float*)d_in[0];
    const float* ring = (const float*)d_in[1];
    const float* prx  = (const float*)d_in[2];
    const float* pry  = (const float*)d_in[3];
    const float* prz  = (const float*)d_in[4];
    vqc_kernel<<<1, 256>>>(psi, ring, prx, pry, prz, (float*)d_out);
}

// round 16
// speedup vs baseline: 1.0388x; 1.0049x over previous
#include <cuda_runtime.h>

// 4-qubit statevector VQC, bidirectional split — FINAL CONVERGED KERNEL.
// Exact champion configuration, measured dur_us 6.624/6.624/6.656/6.624
// across four submissions (R7, R12, R13, R15); all seven perturbations
// (R8-R11, R14) were neutral or regressed. dur_us is at the harness
// graph-replay floor; kernel-active time is <1us at boost clock.
//
//   amp[j] = < (L9..L5)^† e_j | (L4..L0) v >,  L_d = B_d A_d P
//   (P = composed 4-CNOT ring permutation; math verified R2-R15)
//
// Warp 0: forward half (layers 0-4, 10 gather-steps) -> w, stored to smem.
// Warps 1-3: adjoint half for e_0, e_2, e_15 (layers 9..5, 10 gather-steps),
//   concurrent on their own SMSPs; trailing CNOT-permutation folded into the
//   final dot product's gather index.
// Warps 4-7: dedicated producers (load-bearing for overlap, per R10), one
//   Kronecker pair-matrix row per lane (80 rows: 40 forward + 40 adjoint;
//   adjoint 2x2 = same SU(2) builder with 3 sign flips).
// Full-block __syncthreads barriers (named/split barriers regressed, R14).

__global__ void __launch_bounds__(256, 1)
vqc_kernel(const float* __restrict__ psi,
           const float* __restrict__ ring,
           const float* __restrict__ prx,
           const float* __restrict__ pry,
           const float* __restrict__ prz,
           float* __restrict__ out) {
    __shared__ float4 Rows[160];   // 80 rows x 2 float4
    __shared__ float2 wbuf[16];    // forward-half state
    const unsigned FULL = 0xFFFFFFFFu;
    const int l = threadIdx.x;     // 0..255
    const int k = l & 15;
    const int wid = l >> 5;

    auto perm = [](int j) {        // sigma: composed CNOT ring (gather source)
        j = (j & 1) ? (j ^ 8) : j;
        j = (j & 2) ? (j ^ 1) : j;
        j = (j & 4) ? (j ^ 2) : j;
        j = (j & 8) ? (j ^ 4) : j;
        return j;
    };
    auto invperm = [](int j) {     // sigma^{-1}
        j = (j & 8) ? (j ^ 4) : j;
        j = (j & 4) ? (j ^ 2) : j;
        j = (j & 2) ? (j ^ 1) : j;
        j = (j & 1) ? (j ^ 8) : j;
        return j;
    };

    float re = 0.0f, im = 0.0f;

    if (l >= 128) {
        // ---- producers: one Kronecker row per lane ----
        int idx = l - 128;                       // 0..79 (lanes 208+ idle)
        if (idx < 80) {
            int d, p, r, adj;
            if (idx < 40) {                      // forward rows, layers 0-4
                d = idx >> 3; int w = idx & 7; p = w >> 2; r = w & 3; adj = 0;
            } else {                             // adjoint rows, layers 5-9
                int b2 = idx - 40;
                d = 5 + (b2 >> 3); int w = b2 & 7;
                int s = w >> 2;                  // s=0: B^† (pair 1), s=1: A^† (pair 0)
                p = 1 - s; r = w & 3; adj = 1;
            }
            int iA = d * 4 + 2 * p, iB = iA + 1;

            float c1, s1, c2, s2, c3, s3;
            __sincosf(0.5f * prx[iA], &s1, &c1);
            __sincosf(0.5f * pry[iA], &s2, &c2);
            __sincosf(0.5f * prz[iA], &s3, &c3);
            float p1 = c2 * c1, p2 = s2 * s1, p3 = s2 * c1, p4 = c2 * s1;
            float A00re =  fmaf(c3, p1,  s3 * p2);
            float A00im =  fmaf(c3, p2, -s3 * p1);
            float A01re = -fmaf(c3, p3,  s3 * p4);
            float A01im =  fmaf(s3, p3, -c3 * p4);

            __sincosf(0.5f * prx[iB], &s1, &c1);
            __sincosf(0.5f * pry[iB], &s2, &c2);
            __sincosf(0.5f * prz[iB], &s3, &c3);
            p1 = c2 * c1; p2 = s2 * s1; p3 = s2 * c1; p4 = c2 * s1;
            float B00re =  fmaf(c3, p1,  s3 * p2);
            float B00im =  fmaf(c3, p2, -s3 * p1);
            float B01re = -fmaf(c3, p3,  s3 * p4);
            float B01im =  fmaf(s3, p3, -c3 * p4);

            if (adj) {  // M^† of SU(2) [[g00,g01],[-g01*,g00*]] -> (g00*, -g01)
                A00im = -A00im; A01re = -A01re; A01im = -A01im;
                B00im = -B00im; B01re = -B01re; B01im = -B01im;
            }

            // row a of SU(2) M: a==0 -> (g00,g01); a==1 -> (-g01*, g00*)
            int a = r >> 1, b = r & 1;
            float ar0 = a ? -A01re : A00re, ai0 = a ?  A01im : A00im;
            float ar1 = a ?  A00re : A01re, ai1 = a ? -A00im : A01im;
            float br0 = b ? -B01re : B00re, bi0 = b ?  B01im : B00im;
            float br1 = b ?  B00re : B01re, bi1 = b ? -B00im : B01im;

            float g0r = ar0 * br0 - ai0 * bi0, g0i = ar0 * bi0 + ai0 * br0;
            float g1r = ar0 * br1 - ai0 * bi1, g1i = ar0 * bi1 + ai0 * br1;
            float g2r = ar1 * br0 - ai1 * bi0, g2i = ar1 * bi0 + ai1 * br0;
            float g3r = ar1 * br1 - ai1 * bi1, g3i = ar1 * bi1 + ai1 * br1;
            Rows[idx * 2 + 0] = make_float4(g0r, g0i, g1r, g1i);
            Rows[idx * 2 + 1] = make_float4(g2r, g2i, g3r, g3i);
        }
    } else if (l < 32) {
        // ---- warp 0: encoded initial product state ----
        float4 rA4 = reinterpret_cast<const float4*>(ring)[0];
        float4 rB4 = reinterpret_cast<const float4*>(ring)[1];
        float pc = 1.0f, ps = 0.0f;
        float pa = (l < 4) ? psi[l] : 0.0f;
        __sincosf(0.5f * pa, &ps, &pc);
        float rr[4][2] = { { rA4.x, rA4.y }, { rA4.z, rA4.w },
                           { rB4.x, rB4.y }, { rB4.z, rB4.w } };
        float vre[4], vim[4];
#pragma unroll
        for (int n = 0; n < 4; n++) {
            float cn = __shfl_sync(FULL, pc, n);
            float sn = __shfl_sync(FULL, ps, n);
            int b = (k >> (3 - n)) & 1;
            vre[n] =  cn * rr[n][b];
            vim[n] = -sn * rr[n][b ^ 1];
        }
        float are = vre[0] * vre[1] - vim[0] * vim[1];
        float aim = vre[0] * vim[1] + vim[0] * vre[1];
        float bre = vre[2] * vre[3] - vim[2] * vim[3];
        float bim = vre[2] * vim[3] + vim[2] * vre[3];
        re = are * bre - aim * bim;
        im = are * bim + aim * bre;
    } else {
        // ---- warps 1-3: u = e_j ----
        int j = (wid == 1) ? 0 : (wid == 2) ? 2 : 15;
        re = (k == j) ? 1.0f : 0.0f;
        im = 0.0f;
    }

    __syncthreads();   // Rows ready

    // complex 4-term gather step: out = sum_j Row[j] * x[src_j]
    #define GSTEP(BASE, S0, S1, S2, S3)                                        \
    {                                                                          \
        float4 e0 = Rows[(BASE) * 2], e1 = Rows[(BASE) * 2 + 1];               \
        float x0 = __shfl_sync(FULL, re, S0), y0 = __shfl_sync(FULL, im, S0);  \
        float x1 = __shfl_sync(FULL, re, S1), y1 = __shfl_sync(FULL, im, S1);  \
        float x2 = __shfl_sync(FULL, re, S2), y2 = __shfl_sync(FULL, im, S2);  \
        float x3 = __shfl_sync(FULL, re, S3), y3 = __shfl_sync(FULL, im, S3);  \
        float pr0 = e0.x * x0; pr0 = fmaf(-e0.y, y0, pr0);                     \
        float pr1 = e0.z * x1; pr1 = fmaf(-e0.w, y1, pr1);                     \
        float pr2 = e1.x * x2; pr2 = fmaf(-e1.y, y2, pr2);                     \
        float pr3 = e1.z * x3; pr3 = fmaf(-e1.w, y3, pr3);                     \
        float pi0 = e0.x * y0; pi0 = fmaf(e0.y, x0, pi0);                      \
        float pi1 = e0.z * y1; pi1 = fmaf(e0.w, x1, pi1);                      \
        float pi2 = e1.x * y2; pi2 = fmaf(e1.y, x2, pi2);                      \
        float pi3 = e1.z * y3; pi3 = fmaf(e1.w, x3, pi3);                      \
        re = (pr0 + pr1) + (pr2 + pr3);                                        \
        im = (pi0 + pi1) + (pi2 + pi3);                                        \
    }

    if (l < 32) {
        // ---- forward half: layers 0-4 (sigma fused into step A) ----
        const int sA0 = perm((k & 3) | 0),  sA1 = perm((k & 3) | 4);
        const int sA2 = perm((k & 3) | 8),  sA3 = perm((k & 3) | 12);
        const int rAi = (k >> 2) & 3, rBi = k & 3;
        const int sB0 = (k & 12) | 0, sB1 = (k & 12) | 1;
        const int sB2 = (k & 12) | 2, sB3 = (k & 12) | 3;
#pragma unroll
        for (int d = 0; d < 5; d++) {
            GSTEP(d * 8 + rAi,     sA0, sA1, sA2, sA3);
            GSTEP(d * 8 + 4 + rBi, sB0, sB1, sB2, sB3);
        }
        if (l < 16) wbuf[k] = make_float2(re, im);
    } else if (l < 128) {
        // ---- adjoint half: layers 9 down to 5 ----
        // per layer: B^† (bits 2,1), then A^† (bits 8,4);
        // P^{-1} between layers fused into the next B^†'s sources.
        const int rBi = k & 3, rAi = (k >> 2) & 3;
        const int bp0 = (k & 12) | 0, bp1 = (k & 12) | 1;
        const int bp2 = (k & 12) | 2, bp3 = (k & 12) | 3;
        const int bi0 = invperm(bp0), bi1 = invperm(bp1);
        const int bi2 = invperm(bp2), bi3 = invperm(bp3);
        const int ap0 = (k & 3) | 0,  ap1 = (k & 3) | 4;
        const int ap2 = (k & 3) | 8,  ap3 = (k & 3) | 12;
        // d = 9: plain B^† sources
        GSTEP(40 + 4 * 8 + rBi,     bp0, bp1, bp2, bp3);
        GSTEP(40 + 4 * 8 + 4 + rAi, ap0, ap1, ap2, ap3);
#pragma unroll
        for (int d = 8; d >= 5; d--) {
            GSTEP(40 + (d - 5) * 8 + rBi,     bi0, bi1, bi2, bi3);
            GSTEP(40 + (d - 5) * 8 + 4 + rAi, ap0, ap1, ap2, ap3);
        }
    }

    __syncthreads();   // wbuf ready

    if (wid >= 1 && wid <= 3) {
        // ---- dot product: amp_j = sum_m conj(u[m]) * w[sigma(m)] ----
        float2 wv = wbuf[perm(k)];
        float tre = fmaf(re, wv.x,  im * wv.y);
        float tim = fmaf(re, wv.y, -im * wv.x);
#pragma unroll
        for (int m = 1; m < 16; m <<= 1) {
            tre += __shfl_xor_sync(FULL, tre, m);
            tim += __shfl_xor_sync(FULL, tim, m);
        }
        if ((l & 31) == 0) out[wid - 1] = fmaf(tre, tre, tim * tim);
    }
    #undef GSTEP
}

extern "C" void kernel_launch(void* const* d_in, const int* in_sizes, int n_in,
                              void* d_out, int out_size) {
    const float* psi  = (const float*)d_in[0];
    const float* ring = (const float*)d_in[1];
    const float* prx  = (const float*)d_in[2];
    const float* pry  = (const float*)d_in[3];
    const float* prz  = (const float*)d_in[4];
    vqc_kernel<<<1, 256>>>(psi, ring, prx, pry, prz, (float*)d_out);
}